// round 8
// baseline (speedup 1.0000x reference)
#include <cuda_runtime.h>
#include <stdint.h>

// Problem constants (fixed benchmark): N=1e6, IN_C=OUT_C=64, FEAT_C=128, G=4096
#define N_MAX 1000000
#define G_MAX 4096

__device__ int   d_count[G_MAX];
__device__ int   d_offsets[G_MAX + 1];
__device__ int   d_cursor[G_MAX];
__device__ int   d_order[N_MAX];
__device__ float d_mu[G_MAX * 64];
__device__ float d_sig[G_MAX * 64];

// ---------------------------------------------------------------------------
// f32x2 packed helpers (sm_100+)
// ---------------------------------------------------------------------------
__device__ __forceinline__ unsigned long long pack2(float v) {
    unsigned long long r;
    asm("mov.b64 %0, {%1, %1};" : "=l"(r) : "f"(v));
    return r;
}
__device__ __forceinline__ unsigned long long packxy(float x, float y) {
    unsigned long long r;
    asm("mov.b64 %0, {%1, %2};" : "=l"(r) : "f"(x), "f"(y));
    return r;
}
__device__ __forceinline__ unsigned long long ffma2(unsigned long long a,
                                                    unsigned long long b,
                                                    unsigned long long c) {
    unsigned long long d;
    asm("fma.rn.f32x2 %0, %1, %2, %3;" : "=l"(d) : "l"(a), "l"(b), "l"(c));
    return d;
}
__device__ __forceinline__ unsigned long long fadd2(unsigned long long a,
                                                    unsigned long long b) {
    unsigned long long d;
    asm("add.rn.f32x2 %0, %1, %2;" : "=l"(d) : "l"(a), "l"(b));
    return d;
}
__device__ __forceinline__ float2 unpack2(unsigned long long v) {
    float2 f;
    asm("mov.b64 {%0, %1}, %2;" : "=f"(f.x), "=f"(f.y) : "l"(v));
    return f;
}

// ---------------------------------------------------------------------------
// Preprocessing
// ---------------------------------------------------------------------------
__global__ void musig_init_kernel(const float* __restrict__ feat,
                                  const float* __restrict__ Wmu, const float* __restrict__ bmu,
                                  const float* __restrict__ Wsg, const float* __restrict__ bsg,
                                  int G) {
    // fused: zero d_count (grid covers >= G threads)
    int gid = blockIdx.x * blockDim.x + threadIdx.x;
    if (gid < G) d_count[gid] = 0;

    __shared__ float sF[4][128];
    int t  = threadIdx.x;
    int g0 = blockIdx.x * 4;
    for (int i = t; i < 512; i += 256) {
        int gl = i >> 7, k = i & 127;
        int g  = g0 + gl;
        sF[gl][k] = (g < G) ? feat[(size_t)g * 128 + k] : 0.f;
    }
    __syncthreads();
    int gl = t >> 6, c = t & 63;
    int g  = g0 + gl;
    if (g >= G) return;
    float am = bmu[c], as = bsg[c];
#pragma unroll 4
    for (int k = 0; k < 128; k++) {
        float f = sF[gl][k];
        am = fmaf(f, Wmu[k * 64 + c], am);
        as = fmaf(f, Wsg[k * 64 + c], as);
    }
    d_mu[(size_t)g * 64 + c]  = am;
    d_sig[(size_t)g * 64 + c] = as;
}

__global__ void hist_kernel(const int* __restrict__ seg, int n) {
    int i = blockIdx.x * blockDim.x + threadIdx.x;
    if (i < n) atomicAdd(&d_count[seg[i]], 1);
}

__global__ void scan_kernel(int G) {
    __shared__ int wsum[32];
    __shared__ int wpre[32];
    const unsigned full = 0xffffffffu;
    int t = threadIdx.x, lane = t & 31, w = t >> 5;
    int v[4];
    int s = 0;
#pragma unroll
    for (int i = 0; i < 4; i++) {
        int g = 4 * t + i;
        v[i] = (g < G) ? d_count[g] : 0;
        s += v[i];
    }
    int sc = s;
#pragma unroll
    for (int off = 1; off < 32; off <<= 1) {
        int o = __shfl_up_sync(full, sc, off);
        if (lane >= off) sc += o;
    }
    if (lane == 31) wsum[w] = sc;
    __syncthreads();
    if (w == 0) {
        int ws = wsum[lane];
        int p = ws;
#pragma unroll
        for (int off = 1; off < 32; off <<= 1) {
            int o = __shfl_up_sync(full, p, off);
            if (lane >= off) p += o;
        }
        wpre[lane] = p - ws;
    }
    __syncthreads();
    int excl = wpre[w] + sc - s;
#pragma unroll
    for (int i = 0; i < 4; i++) {
        int g = 4 * t + i;
        if (g < G) {
            d_offsets[g] = excl;
            d_cursor[g]  = excl;
            excl += v[i];
        }
    }
    if (t == 1023) d_offsets[G] = excl;
}

__global__ void scatter_kernel(const int* __restrict__ seg, int n) {
    int i = blockIdx.x * blockDim.x + threadIdx.x;
    if (i < n) {
        int p = atomicAdd(&d_cursor[seg[i]], 1);
        d_order[p] = i;
    }
}

// ---------------------------------------------------------------------------
// Group kernel, FFMA2 with smem-duplicated x (transposed), no packs in loop.
//   256 threads, 1 CTA/SM (255-reg budget, no spills).
//   Thread tile: 2 rows (tr = t>>3, rows 2tr..2tr+1) x 8 cols (tc = t&7,
//   cols 8tc..8tc+7 as 4 f32x2 col-pairs).
//   sX layout (per 64-row chunk, double buffered): [k][2*row]=[k][2*row+1]=x[row][k],
//   pitch XPITCH floats -> one LDS.128 at [k*XPITCH + 4*tr] yields both
//   row-broadcast pairs. W row-major: ulonglong2 = 2 native col-pairs.
//   h cached row-major in sH with float4-rotation swizzle (group (f+row%16)%16).
// ---------------------------------------------------------------------------
#define CAP 320
#define CHUNK 64
#define XPITCH 132
#define XBUF (64 * XPITCH)

__device__ __forceinline__ void load_rows(const float* __restrict__ x,
                                          int off, int base, int cnt,
                                          int sr, int sq, float4 v[4]) {
    int gr = base + sr;
    if (gr < cnt) {
        int gi = __ldg(&d_order[off + gr]);
        const float4* xr = reinterpret_cast<const float4*>(x + (size_t)gi * 64);
#pragma unroll
        for (int i = 0; i < 4; i++) v[i] = xr[sq * 4 + i];
    } else {
#pragma unroll
        for (int i = 0; i < 4; i++) v[i] = make_float4(0.f, 0.f, 0.f, 0.f);
    }
}

// scatter thread's 16 x-values (row sr, k = 16*sq .. 16*sq+15) transposed+duplicated
__device__ __forceinline__ void sts_T(float* __restrict__ sXb,
                                      int sr, int sq, const float4 v[4]) {
#pragma unroll
    for (int i = 0; i < 4; i++) {
        int k0 = 16 * sq + 4 * i;
        *reinterpret_cast<unsigned long long*>(sXb + (k0 + 0) * XPITCH + 2 * sr) = pack2(v[i].x);
        *reinterpret_cast<unsigned long long*>(sXb + (k0 + 1) * XPITCH + 2 * sr) = pack2(v[i].y);
        *reinterpret_cast<unsigned long long*>(sXb + (k0 + 2) * XPITCH + 2 * sr) = pack2(v[i].z);
        *reinterpret_cast<unsigned long long*>(sXb + (k0 + 3) * XPITCH + 2 * sr) = pack2(v[i].w);
    }
}

__device__ __forceinline__ void chunk_gemm2(const float* __restrict__ sXb,
                                            const float* __restrict__ sW,
                                            const unsigned long long bp[4],
                                            int tr, int tc,
                                            unsigned long long acc[2][4]) {
#pragma unroll
    for (int p = 0; p < 4; p++) { acc[0][p] = bp[p]; acc[1][p] = bp[p]; }
    const float* xb = sXb + 4 * tr;
    const float* wb = sW + 8 * tc;
#pragma unroll 16
    for (int k = 0; k < 64; k++) {
        ulonglong2 xv = *reinterpret_cast<const ulonglong2*>(xb + k * XPITCH);
        ulonglong2 wA = *reinterpret_cast<const ulonglong2*>(wb + k * 64);
        ulonglong2 wB = *reinterpret_cast<const ulonglong2*>(wb + k * 64 + 4);
        acc[0][0] = ffma2(xv.x, wA.x, acc[0][0]);
        acc[0][1] = ffma2(xv.x, wA.y, acc[0][1]);
        acc[0][2] = ffma2(xv.x, wB.x, acc[0][2]);
        acc[0][3] = ffma2(xv.x, wB.y, acc[0][3]);
        acc[1][0] = ffma2(xv.y, wA.x, acc[1][0]);
        acc[1][1] = ffma2(xv.y, wA.y, acc[1][1]);
        acc[1][2] = ffma2(xv.y, wB.x, acc[1][2]);
        acc[1][3] = ffma2(xv.y, wB.y, acc[1][3]);
    }
}

__global__ __launch_bounds__(256, 1) void group_kernel(const float* __restrict__ x,
                                                       const float* __restrict__ Wfc,
                                                       const float* __restrict__ bfc,
                                                       float* __restrict__ out) {
    extern __shared__ float sm[];
    float* sW     = sm;                    // 4096
    float* sX     = sm + 4096;             // 2 * XBUF
    float* sH     = sX + 2 * XBUF;         // CAP*64
    float* sSum   = sH + CAP * 64;         // 64
    float* sSq    = sSum + 64;             // 64
    float* sMu    = sSq + 64;              // 64
    float* sSig   = sMu + 64;              // 64
    float* sScale = sSig + 64;             // 64
    float* sShift = sScale + 64;           // 64

    int t   = threadIdx.x;
    int g   = blockIdx.x;
    int off = d_offsets[g];
    int cnt = d_offsets[g + 1] - off;

    for (int i = t; i < 4096; i += 256) sW[i] = Wfc[i];
    if (t < 64) {
        sMu[t]  = d_mu[(size_t)g * 64 + t];
        sSig[t] = d_sig[(size_t)g * 64 + t];
        sSum[t] = 0.f;
        sSq[t]  = 0.f;
    }
    int tr = t >> 3, tc = t & 7;       // GEMM tile coords
    int sr = t >> 2, sq = t & 3;       // staging coords
    unsigned long long bp[4];
    {
        float4 ba = reinterpret_cast<const float4*>(bfc)[tc * 2];
        float4 bb = reinterpret_cast<const float4*>(bfc)[tc * 2 + 1];
        bp[0] = packxy(ba.x, ba.y);
        bp[1] = packxy(ba.z, ba.w);
        bp[2] = packxy(bb.x, bb.y);
        bp[3] = packxy(bb.z, bb.w);
    }
    __syncthreads();
    if (cnt == 0) return;

    bool cached = (cnt <= CAP);
    int  nch    = (cnt + CHUNK - 1) >> 6;

    unsigned long long csum[4], csq[4];
#pragma unroll
    for (int p = 0; p < 4; p++) { csum[p] = 0ull; csq[p] = 0ull; }
    unsigned long long acc[2][4];

    if (cached) {
        // pipelined: LDG(c+1) under GEMM(c); STS(c+1) into other buffer; 1 bar/chunk
        float4 pv[4];
        load_rows(x, off, 0, cnt, sr, sq, pv);
        sts_T(sX, sr, sq, pv);
        __syncthreads();
        for (int c = 0; c < nch; c++) {
            int base = c << 6;
            bool havnext = (c + 1 < nch);
            if (havnext) load_rows(x, off, base + 64, cnt, sr, sq, pv);
            chunk_gemm2(sX + (c & 1) * XBUF, sW, bp, tr, tc, acc);
            // stats (masked per row)
#pragma unroll
            for (int r = 0; r < 2; r++) {
                if (base + 2 * tr + r < cnt) {
#pragma unroll
                    for (int p = 0; p < 4; p++) {
                        csum[p] = fadd2(csum[p], acc[r][p]);
                        csq[p]  = ffma2(acc[r][p], acc[r][p], csq[p]);
                    }
                }
            }
            // cache h rows (row-major + rotation swizzle)
#pragma unroll
            for (int r = 0; r < 2; r++) {
                int lr  = 2 * tr + r;
                int rot = lr & 15;                       // base % 16 == 0
                float2 u0 = unpack2(acc[r][0]);
                float2 u1 = unpack2(acc[r][1]);
                float2 u2 = unpack2(acc[r][2]);
                float2 u3 = unpack2(acc[r][3]);
                float4* row4 = reinterpret_cast<float4*>(sH + (size_t)(base + lr) * 64);
                row4[(2 * tc + rot) & 15]     = make_float4(u0.x, u0.y, u1.x, u1.y);
                row4[(2 * tc + 1 + rot) & 15] = make_float4(u2.x, u2.y, u3.x, u3.y);
            }
            if (havnext) sts_T(sX + ((c + 1) & 1) * XBUF, sr, sq, pv);
            __syncthreads();
        }
    } else {
        // rare big group: single-buffer staged GEMM, stats only
        float4 pv[4];
        for (int c = 0; c < nch; c++) {
            int base = c << 6;
            load_rows(x, off, base, cnt, sr, sq, pv);
            sts_T(sX, sr, sq, pv);
            __syncthreads();
            chunk_gemm2(sX, sW, bp, tr, tc, acc);
#pragma unroll
            for (int r = 0; r < 2; r++) {
                if (base + 2 * tr + r < cnt) {
#pragma unroll
                    for (int p = 0; p < 4; p++) {
                        csum[p] = fadd2(csum[p], acc[r][p]);
                        csq[p]  = ffma2(acc[r][p], acc[r][p], csq[p]);
                    }
                }
            }
            __syncthreads();
        }
    }

    // -------- reduce stats: lanes {l, l+8, l+16, l+24} share tc --------
    const unsigned full = 0xffffffffu;
#pragma unroll
    for (int p = 0; p < 4; p++) {
        csum[p] = fadd2(csum[p], __shfl_down_sync(full, csum[p], 16));
        csum[p] = fadd2(csum[p], __shfl_down_sync(full, csum[p], 8));
        csq[p]  = fadd2(csq[p],  __shfl_down_sync(full, csq[p], 16));
        csq[p]  = fadd2(csq[p],  __shfl_down_sync(full, csq[p], 8));
    }
    if ((t & 31) < 8) {
#pragma unroll
        for (int p = 0; p < 4; p++) {
            float2 us = unpack2(csum[p]);
            float2 uq = unpack2(csq[p]);
            atomicAdd(&sSum[tc * 8 + 2 * p],     us.x);
            atomicAdd(&sSum[tc * 8 + 2 * p + 1], us.y);
            atomicAdd(&sSq[tc * 8 + 2 * p],      uq.x);
            atomicAdd(&sSq[tc * 8 + 2 * p + 1],  uq.y);
        }
    }
    __syncthreads();

    if (t < 64) {
        float inv_n = 1.0f / (float)cnt;
        float mean  = sSum[t] * inv_n;
        float var   = sSq[t] * inv_n - mean * mean;
        var = fmaxf(var, 0.f);
        float sc = sSig[t] * rsqrtf(var + 1e-14f);
        sScale[t] = sc;
        sShift[t] = sMu[t] - mean * sc;
    }
    __syncthreads();

    // -------- pass 2: apply + write --------
    if (cached) {
        int w = t >> 5, l = t & 31;
        float2 sc2 = reinterpret_cast<float2*>(sScale)[l];
        float2 sh2 = reinterpret_cast<float2*>(sShift)[l];
        for (int j = w; j < cnt; j += 8) {
            int gi  = __ldg(&d_order[off + j]);
            int col = (2 * l + 4 * (j & 15)) & 63;
            float2 h2 = *reinterpret_cast<float2*>(&sH[(size_t)j * 64 + col]);
            float2 o;
            o.x = fmaxf(fmaf(h2.x, sc2.x, sh2.x), 0.f);
            o.y = fmaxf(fmaf(h2.y, sc2.y, sh2.y), 0.f);
            reinterpret_cast<float2*>(out + (size_t)gi * 64)[l] = o;
        }
    } else {
        // recompute h per chunk and write directly
        float4 pv[4];
        float2 sc2[4], sh2[4];
#pragma unroll
        for (int p = 0; p < 4; p++) {
            sc2[p] = reinterpret_cast<float2*>(sScale)[tc * 4 + p];
            sh2[p] = reinterpret_cast<float2*>(sShift)[tc * 4 + p];
        }
        for (int c = 0; c < nch; c++) {
            int base = c << 6;
            load_rows(x, off, base, cnt, sr, sq, pv);
            sts_T(sX, sr, sq, pv);
            __syncthreads();
            chunk_gemm2(sX, sW, bp, tr, tc, acc);
#pragma unroll
            for (int r = 0; r < 2; r++) {
                int gr = base + 2 * tr + r;
                if (gr < cnt) {
                    int gi = __ldg(&d_order[off + gr]);
                    float2 u0 = unpack2(acc[r][0]);
                    float2 u1 = unpack2(acc[r][1]);
                    float2 u2 = unpack2(acc[r][2]);
                    float2 u3 = unpack2(acc[r][3]);
                    float4 oA, oB;
                    oA.x = fmaxf(fmaf(u0.x, sc2[0].x, sh2[0].x), 0.f);
                    oA.y = fmaxf(fmaf(u0.y, sc2[0].y, sh2[0].y), 0.f);
                    oA.z = fmaxf(fmaf(u1.x, sc2[1].x, sh2[1].x), 0.f);
                    oA.w = fmaxf(fmaf(u1.y, sc2[1].y, sh2[1].y), 0.f);
                    oB.x = fmaxf(fmaf(u2.x, sc2[2].x, sh2[2].x), 0.f);
                    oB.y = fmaxf(fmaf(u2.y, sc2[2].y, sh2[2].y), 0.f);
                    oB.z = fmaxf(fmaf(u3.x, sc2[3].x, sh2[3].x), 0.f);
                    oB.w = fmaxf(fmaf(u3.y, sc2[3].y, sh2[3].y), 0.f);
                    reinterpret_cast<float4*>(out + (size_t)gi * 64)[tc * 2]     = oA;
                    reinterpret_cast<float4*>(out + (size_t)gi * 64)[tc * 2 + 1] = oB;
                }
            }
            __syncthreads();
        }
    }
}

// ---------------------------------------------------------------------------
extern "C" void kernel_launch(void* const* d_in, const int* in_sizes, int n_in,
                              void* d_out, int out_size) {
    int wi = (n_in >= 10) ? 4 : 3;
    const float* x    = (const float*)d_in[0];
    const float* feat = (const float*)d_in[1];
    const int*   seg  = (const int*)d_in[2];
    const float* Wfc  = (const float*)d_in[wi + 0];
    const float* bfc  = (const float*)d_in[wi + 1];
    const float* Wmu  = (const float*)d_in[wi + 2];
    const float* bmu  = (const float*)d_in[wi + 3];
    const float* Wsg  = (const float*)d_in[wi + 4];
    const float* bsg  = (const float*)d_in[wi + 5];
    float* out = (float*)d_out;

    int n = in_sizes[0] / 64;
    int G = in_sizes[1] / 128;

    const size_t smem = (size_t)(4096 + 2 * XBUF + CAP * 64 + 6 * 64) * sizeof(float);
    cudaFuncSetAttribute(group_kernel, cudaFuncAttributeMaxDynamicSharedMemorySize,
                         (int)smem);

    musig_init_kernel<<<(G + 3) / 4, 256>>>(feat, Wmu, bmu, Wsg, bsg, G);
    hist_kernel<<<(n + 255) / 256, 256>>>(seg, n);
    scan_kernel<<<1, 1024>>>(G);
    scatter_kernel<<<(n + 255) / 256, 256>>>(seg, n);
    group_kernel<<<G, 256, smem>>>(x, Wfc, bfc, out);
}

// round 9
// speedup vs baseline: 2.1526x; 2.1526x over previous
#include <cuda_runtime.h>
#include <stdint.h>

// Problem constants (fixed benchmark): N=1e6, IN_C=OUT_C=64, FEAT_C=128, G=4096
#define N_MAX 1000000
#define G_MAX 4096

__device__ int   d_count[G_MAX];
__device__ int   d_offsets[G_MAX + 1];
__device__ int   d_cursor[G_MAX];
__device__ int   d_order[N_MAX];
__device__ float d_mu[G_MAX * 64];
__device__ float d_sig[G_MAX * 64];

// ---------------------------------------------------------------------------
// Preprocessing
// ---------------------------------------------------------------------------
// mu/sig GEMMs + fused d_count zeroing (grid covers >= G threads)
__global__ void musig_init_kernel(const float* __restrict__ feat,
                                  const float* __restrict__ Wmu, const float* __restrict__ bmu,
                                  const float* __restrict__ Wsg, const float* __restrict__ bsg,
                                  int G) {
    int gid = blockIdx.x * blockDim.x + threadIdx.x;
    if (gid < G) d_count[gid] = 0;

    __shared__ float sF[4][128];
    int t  = threadIdx.x;
    int g0 = blockIdx.x * 4;
    for (int i = t; i < 512; i += 256) {
        int gl = i >> 7, k = i & 127;
        int g  = g0 + gl;
        sF[gl][k] = (g < G) ? feat[(size_t)g * 128 + k] : 0.f;
    }
    __syncthreads();
    int gl = t >> 6, c = t & 63;
    int g  = g0 + gl;
    if (g >= G) return;
    float am = bmu[c], as = bsg[c];
#pragma unroll 4
    for (int k = 0; k < 128; k++) {
        float f = sF[gl][k];
        am = fmaf(f, Wmu[k * 64 + c], am);
        as = fmaf(f, Wsg[k * 64 + c], as);
    }
    d_mu[(size_t)g * 64 + c]  = am;
    d_sig[(size_t)g * 64 + c] = as;
}

__global__ void hist_kernel(const int* __restrict__ seg, int n) {
    int i = blockIdx.x * blockDim.x + threadIdx.x;
    if (i < n) atomicAdd(&d_count[seg[i]], 1);
}

// Shuffle-based scan of up to 4096 counts (1024 threads x 4 each, 2 barriers)
__global__ void scan_kernel(int G) {
    __shared__ int wsum[32];
    __shared__ int wpre[32];
    const unsigned full = 0xffffffffu;
    int t = threadIdx.x, lane = t & 31, w = t >> 5;
    int v[4];
    int s = 0;
#pragma unroll
    for (int i = 0; i < 4; i++) {
        int g = 4 * t + i;
        v[i] = (g < G) ? d_count[g] : 0;
        s += v[i];
    }
    int sc = s;
#pragma unroll
    for (int off = 1; off < 32; off <<= 1) {
        int o = __shfl_up_sync(full, sc, off);
        if (lane >= off) sc += o;
    }
    if (lane == 31) wsum[w] = sc;
    __syncthreads();
    if (w == 0) {
        int ws = wsum[lane];
        int p = ws;
#pragma unroll
        for (int off = 1; off < 32; off <<= 1) {
            int o = __shfl_up_sync(full, p, off);
            if (lane >= off) p += o;
        }
        wpre[lane] = p - ws;
    }
    __syncthreads();
    int excl = wpre[w] + sc - s;
#pragma unroll
    for (int i = 0; i < 4; i++) {
        int g = 4 * t + i;
        if (g < G) {
            d_offsets[g] = excl;
            d_cursor[g]  = excl;
            excl += v[i];
        }
    }
    if (t == 1023) d_offsets[G] = excl;
}

__global__ void scatter_kernel(const int* __restrict__ seg, int n) {
    int i = blockIdx.x * blockDim.x + threadIdx.x;
    if (i < n) {
        int p = atomicAdd(&d_cursor[seg[i]], 1);
        d_order[p] = i;
    }
}

// ---------------------------------------------------------------------------
// Per-group fused kernel (scalar FFMA 4x4 tile — the proven 500us structure)
// with (new) LDG prefetch pipelining and 1 barrier + 1 syncwarp per chunk.
// SMEM rows use the float4 rotation swizzle: float4 group f of row r lives at
// index (f + r%16)%16 -> conflict-free for k-major and c-major access.
// ---------------------------------------------------------------------------
#define CAP 320          // cached h rows (5 chunks of 64)
#define CHUNK 64

__device__ __forceinline__ void chunk_gemm(const float* __restrict__ sH,
                                           const float* __restrict__ sW,
                                           const float bf[4],
                                           int slot, int rb, int cb,
                                           float acc[4][4]) {
#pragma unroll
    for (int r = 0; r < 4; r++) {
        acc[r][0] = bf[0]; acc[r][1] = bf[1]; acc[r][2] = bf[2]; acc[r][3] = bf[3];
    }
    const float* rowp[4];
    int rot4[4];
#pragma unroll
    for (int r = 0; r < 4; r++) {
        int lr  = rb * 4 + r;            // local row in chunk (0..63)
        rowp[r] = sH + (size_t)(slot + lr) * 64;
        rot4[r] = lr & 15;               // float4 rotation
    }
#pragma unroll 4
    for (int k4 = 0; k4 < 16; k4++) {
        float4 xv[4];
#pragma unroll
        for (int r = 0; r < 4; r++) {
            int f = (k4 + rot4[r]) & 15;
            xv[r] = reinterpret_cast<const float4*>(rowp[r])[f];
        }
#pragma unroll
        for (int kk = 0; kk < 4; kk++) {
            int k     = k4 * 4 + kk;
            float4 w4 = reinterpret_cast<const float4*>(sW + k * 64)[cb];
#pragma unroll
            for (int r = 0; r < 4; r++) {
                float xk = (kk == 0) ? xv[r].x : (kk == 1) ? xv[r].y : (kk == 2) ? xv[r].z : xv[r].w;
                acc[r][0] = fmaf(xk, w4.x, acc[r][0]);
                acc[r][1] = fmaf(xk, w4.y, acc[r][1]);
                acc[r][2] = fmaf(xk, w4.z, acc[r][2]);
                acc[r][3] = fmaf(xk, w4.w, acc[r][3]);
            }
        }
    }
}

__device__ __forceinline__ void load_rows(const float* __restrict__ x,
                                          int off, int base, int cnt,
                                          int sr, int sq, float4 v[4]) {
    int gr = base + sr;
    if (gr < cnt) {
        int gi = __ldg(&d_order[off + gr]);
        const float4* xr = reinterpret_cast<const float4*>(x + (size_t)gi * 64);
#pragma unroll
        for (int i = 0; i < 4; i++) v[i] = xr[sq * 4 + i];
    } else {
#pragma unroll
        for (int i = 0; i < 4; i++) v[i] = make_float4(0.f, 0.f, 0.f, 0.f);
    }
}

__device__ __forceinline__ void sts_rows(float* __restrict__ sH, int slot,
                                         int sr, int sq, const float4 v[4]) {
    float4* row4 = reinterpret_cast<float4*>(sH + (size_t)(slot + sr) * 64);
    int rot = sr & 15;                        // slot is multiple of 64
#pragma unroll
    for (int i = 0; i < 4; i++) row4[(sq * 4 + i + rot) & 15] = v[i];
}

__global__ __launch_bounds__(256, 2) void group_kernel(const float* __restrict__ x,
                                                       const float* __restrict__ Wfc,
                                                       const float* __restrict__ bfc,
                                                       float* __restrict__ out) {
    extern __shared__ float sm[];
    float* sW     = sm;                 // 4096
    float* sH     = sm + 4096;          // CAP*64
    float* sSum   = sH + CAP * 64;      // 64
    float* sSq    = sSum + 64;          // 64
    float* sMu    = sSq + 64;           // 64
    float* sSig   = sMu + 64;           // 64
    float* sScale = sSig + 64;          // 64
    float* sShift = sScale + 64;        // 64

    int t   = threadIdx.x;
    int g   = blockIdx.x;
    int off = d_offsets[g];
    int cnt = d_offsets[g + 1] - off;

    for (int i = t; i < 4096; i += 256) sW[i] = Wfc[i];
    if (t < 64) {
        sMu[t]  = d_mu[(size_t)g * 64 + t];
        sSig[t] = d_sig[(size_t)g * 64 + t];
        sSum[t] = 0.f;
        sSq[t]  = 0.f;
    }
    int rb = t >> 4, cb = t & 15;
    float bf[4];
    {
        float4 b4 = reinterpret_cast<const float4*>(bfc)[cb];
        bf[0] = b4.x; bf[1] = b4.y; bf[2] = b4.z; bf[3] = b4.w;
    }
    __syncthreads();
    if (cnt == 0) return;

    bool cached = (cnt <= CAP);
    int  nch    = (cnt + CHUNK - 1) >> 6;
    int  sr = t >> 2, sq = t & 3;      // staging: row, quarter

    float csum[4] = {0.f, 0.f, 0.f, 0.f};
    float csq[4]  = {0.f, 0.f, 0.f, 0.f};
    float acc[4][4];

    if (cached) {
        // ---- pass 1, pipelined: LDG(c+1) under GEMM(c); 1 barrier/chunk ----
        float4 pv[4];
        load_rows(x, off, 0, cnt, sr, sq, pv);
        sts_rows(sH, 0, sr, sq, pv);
        __syncthreads();
        for (int c = 0; c < nch; c++) {
            int base = c << 6;
            bool havnext = (c + 1 < nch);
            if (havnext) load_rows(x, off, base + 64, cnt, sr, sq, pv);  // LDG in flight
            chunk_gemm(sH, sW, bf, base, rb, cb, acc);
#pragma unroll
            for (int r = 0; r < 4; r++) {
                if (base + rb * 4 + r < cnt) {
#pragma unroll
                    for (int j = 0; j < 4; j++) {
                        float h = acc[r][j];
                        csum[j] += h;
                        csq[j]   = fmaf(h, h, csq[j]);
                    }
                }
            }
            // row lr of this slot is read & written only by threads sharing rb,
            // which all live in warp rb>>1 -> warp-level sync suffices.
            __syncwarp();
#pragma unroll
            for (int r = 0; r < 4; r++) {
                int lr = rb * 4 + r;
                reinterpret_cast<float4*>(sH + (size_t)(base + lr) * 64)[(cb + (lr & 15)) & 15] =
                    make_float4(acc[r][0], acc[r][1], acc[r][2], acc[r][3]);
            }
            if (havnext) sts_rows(sH, base + 64, sr, sq, pv);  // fresh slot, no readers yet
            __syncthreads();
        }
    } else {
        // ---- rare big-group path: plain staged GEMM into slot 0 ----
        float4 pv[4];
        for (int c = 0; c < nch; c++) {
            int base = c << 6;
            load_rows(x, off, base, cnt, sr, sq, pv);
            sts_rows(sH, 0, sr, sq, pv);
            __syncthreads();
            chunk_gemm(sH, sW, bf, 0, rb, cb, acc);
#pragma unroll
            for (int r = 0; r < 4; r++) {
                if (base + rb * 4 + r < cnt) {
#pragma unroll
                    for (int j = 0; j < 4; j++) {
                        float h = acc[r][j];
                        csum[j] += h;
                        csq[j]   = fmaf(h, h, csq[j]);
                    }
                }
            }
            __syncthreads();
        }
    }

    // -------- reduce stats --------
    unsigned full = 0xffffffffu;
#pragma unroll
    for (int j = 0; j < 4; j++) {
        csum[j] += __shfl_down_sync(full, csum[j], 16);
        csq[j]  += __shfl_down_sync(full, csq[j], 16);
    }
    if ((t & 31) < 16) {
#pragma unroll
        for (int j = 0; j < 4; j++) {
            atomicAdd(&sSum[cb * 4 + j], csum[j]);
            atomicAdd(&sSq[cb * 4 + j], csq[j]);
        }
    }
    __syncthreads();

    if (t < 64) {
        float inv_n = 1.0f / (float)cnt;
        float mean  = sSum[t] * inv_n;
        float var   = sSq[t] * inv_n - mean * mean;
        var = fmaxf(var, 0.f);
        float sc = sSig[t] * rsqrtf(var + 1e-14f);
        sScale[t] = sc;
        sShift[t] = sMu[t] - mean * sc;
    }
    __syncthreads();

    // -------- pass 2: apply + write --------
    if (cached) {
        int w = t >> 5, l = t & 31;
        float2 sc2 = reinterpret_cast<float2*>(sScale)[l];
        float2 sh2 = reinterpret_cast<float2*>(sShift)[l];
        for (int j = w; j < cnt; j += 8) {
            int gi  = __ldg(&d_order[off + j]);
            int col = (2 * l + 4 * (j & 15)) & 63;
            float2 h2 = *reinterpret_cast<float2*>(&sH[(size_t)j * 64 + col]);
            float2 o;
            o.x = fmaxf(fmaf(h2.x, sc2.x, sh2.x), 0.f);
            o.y = fmaxf(fmaf(h2.y, sc2.y, sh2.y), 0.f);
            reinterpret_cast<float2*>(out + (size_t)gi * 64)[l] = o;
        }
    } else {
        // recompute h per chunk and write directly
        float4 pv[4];
        float4 sc4 = reinterpret_cast<float4*>(sScale)[cb];
        float4 sh4 = reinterpret_cast<float4*>(sShift)[cb];
        for (int c = 0; c < nch; c++) {
            int base = c << 6;
            load_rows(x, off, base, cnt, sr, sq, pv);
            sts_rows(sH, 0, sr, sq, pv);
            __syncthreads();
            chunk_gemm(sH, sW, bf, 0, rb, cb, acc);
#pragma unroll
            for (int r = 0; r < 4; r++) {
                int gr = base + rb * 4 + r;
                if (gr < cnt) {
                    int gi = __ldg(&d_order[off + gr]);
                    float4 o;
                    o.x = fmaxf(fmaf(acc[r][0], sc4.x, sh4.x), 0.f);
                    o.y = fmaxf(fmaf(acc[r][1], sc4.y, sh4.y), 0.f);
                    o.z = fmaxf(fmaf(acc[r][2], sc4.z, sh4.z), 0.f);
                    o.w = fmaxf(fmaf(acc[r][3], sc4.w, sh4.w), 0.f);
                    reinterpret_cast<float4*>(out + (size_t)gi * 64)[cb] = o;
                }
            }
            __syncthreads();
        }
    }
}

// ---------------------------------------------------------------------------
extern "C" void kernel_launch(void* const* d_in, const int* in_sizes, int n_in,
                              void* d_out, int out_size) {
    int wi = (n_in >= 10) ? 4 : 3;
    const float* x    = (const float*)d_in[0];
    const float* feat = (const float*)d_in[1];
    const int*   seg  = (const int*)d_in[2];
    const float* Wfc  = (const float*)d_in[wi + 0];
    const float* bfc  = (const float*)d_in[wi + 1];
    const float* Wmu  = (const float*)d_in[wi + 2];
    const float* bmu  = (const float*)d_in[wi + 3];
    const float* Wsg  = (const float*)d_in[wi + 4];
    const float* bsg  = (const float*)d_in[wi + 5];
    float* out = (float*)d_out;

    int n = in_sizes[0] / 64;
    int G = in_sizes[1] / 128;

    const size_t smem = (size_t)(4096 + CAP * 64 + 6 * 64) * sizeof(float); // 99840 B
    cudaFuncSetAttribute(group_kernel, cudaFuncAttributeMaxDynamicSharedMemorySize,
                         (int)smem);

    musig_init_kernel<<<(G + 3) / 4, 256>>>(feat, Wmu, bmu, Wsg, bsg, G);
    hist_kernel<<<(n + 255) / 256, 256>>>(seg, n);
    scan_kernel<<<1, 1024>>>(G);
    scatter_kernel<<<(n + 255) / 256, 256>>>(seg, n);
    group_kernel<<<G, 256, smem>>>(x, Wfc, bfc, out);
}